// round 2
// baseline (speedup 1.0000x reference)
#include <cuda_runtime.h>
#include <math.h>

#define SEQ     2048
#define EMBD    1024
#define STATE   1024
#define QIN     2048
#define QUERY   256
#define NKB     10000
#define VALUE   512
#define LSTMIN  1536
#define DECIN   2560
#define NTOK    32000
#define NB      148
#define NT      512

// ---------------- device scratch (no allocations allowed) ----------------
__device__ __align__(16) float g_dec_in[SEQ * DECIN];   // [emb | kb_out | lstm_states]
__device__ __align__(16) float g_A1[SEQ * QIN];
__device__ __align__(16) float g_Gx[SEQ * 4 * STATE];
__device__ __align__(16) float g_Wq1T[QIN * STATE];     // [2048 out][1024 k]
__device__ __align__(16) float g_Wq2T[QUERY * QIN];     // [256 out][2048 k]
__device__ __align__(16) float g_qh[QIN];
__device__ __align__(16) float g_q[QUERY];
__device__ __align__(16) float g_pval[VALUE * 152];
__device__ __align__(16) float g_pz[NB];
__device__ __align__(16) float g_val[VALUE];
__device__ float g_invZ;
__device__ __align__(16) float g_hxA[STATE];
__device__ __align__(16) float g_hxB[STATE];
__device__ __align__(16) float g_cx[STATE];
__device__ volatile unsigned g_gen;
__device__ unsigned g_cnt;

// ---------------- helpers ----------------
__device__ __forceinline__ float dot4(float4 a, float4 b) {
    return a.x * b.x + a.y * b.y + a.z * b.z + a.w * b.w;
}
__device__ __forceinline__ float sigmoidf_(float x) { return 1.0f / (1.0f + expf(-x)); }
__device__ __forceinline__ float wred(float a) {
#pragma unroll
    for (int o = 16; o; o >>= 1) a += __shfl_xor_sync(0xffffffffu, a, o);
    return a;
}

__device__ __forceinline__ void grid_sync(unsigned &tgt) {
    __syncthreads();
    if (threadIdx.x == 0) {
        __threadfence();
        if (atomicAdd(&g_cnt, 1u) == NB - 1) {
            g_cnt = 0;
            __threadfence();
            g_gen = tgt;
        } else {
            while (g_gen != tgt) { }
        }
        __threadfence();
    }
    __syncthreads();
    tgt++;
}

// ---------------- embedding gather + state init ----------------
__global__ void embed_init_kernel(const int* __restrict__ ids,
                                  const float* __restrict__ encW) {
    int t = blockIdx.x;
    int id = ids[t];
    for (int e = threadIdx.x; e < EMBD; e += blockDim.x)
        g_dec_in[(size_t)t * DECIN + e] = encW[(size_t)id * EMBD + e];
    if (blockIdx.x == 0) {
        for (int i = threadIdx.x; i < STATE; i += blockDim.x) {
            g_hxA[i] = 0.0f; g_hxB[i] = 0.0f; g_cx[i] = 0.0f;
        }
    }
}

// ---------------- transpose: dst[c*M + r] = src[r*N + c]  (src is MxN) ----------------
__global__ void transpose_kernel(const float* __restrict__ src, float* __restrict__ dst,
                                 int M, int N) {
    __shared__ float tile[32][33];
    int c0 = blockIdx.x * 32, r0 = blockIdx.y * 32;
    int c = c0 + threadIdx.x;
#pragma unroll
    for (int j = 0; j < 32; j += 8) {
        int r = r0 + threadIdx.y + j;
        tile[threadIdx.y + j][threadIdx.x] = src[(size_t)r * N + c];
    }
    __syncthreads();
    int rr = r0 + threadIdx.x;
#pragma unroll
    for (int j = 0; j < 32; j += 8) {
        int cc = c0 + threadIdx.y + j;
        dst[(size_t)cc * M + rr] = tile[threadIdx.x][threadIdx.y + j];
    }
}

// ------- tiled SGEMM: C[m][n] = sum_k A[m][k] * (BT ? B[n][k] : B[k][n]) + bias -------
template <bool BT>
__global__ __launch_bounds__(256) void sgemm_kernel(
    const float* __restrict__ A, int lda,
    const float* __restrict__ B, int ldb,
    float* __restrict__ C, int ldc, int K,
    const float* __restrict__ bias1, const float* __restrict__ bias2) {
    __shared__ float As[8][128];
    __shared__ float Bs[8][128];
    int m0 = blockIdx.y * 128, n0 = blockIdx.x * 128;
    int tid = threadIdx.x;
    int tx = tid & 15, ty = tid >> 4;
    int ar = tid >> 1, ac = (tid & 1) * 4;
    int bk = tid >> 5, bn = (tid & 31) * 4;
    float acc[8][8];
#pragma unroll
    for (int i = 0; i < 8; i++)
#pragma unroll
        for (int j = 0; j < 8; j++) acc[i][j] = 0.0f;

    for (int k0 = 0; k0 < K; k0 += 8) {
        float4 av = *(const float4*)(A + (size_t)(m0 + ar) * lda + k0 + ac);
        As[ac + 0][ar] = av.x; As[ac + 1][ar] = av.y;
        As[ac + 2][ar] = av.z; As[ac + 3][ar] = av.w;
        if (BT) {
            float4 bv = *(const float4*)(B + (size_t)(n0 + ar) * ldb + k0 + ac);
            Bs[ac + 0][ar] = bv.x; Bs[ac + 1][ar] = bv.y;
            Bs[ac + 2][ar] = bv.z; Bs[ac + 3][ar] = bv.w;
        } else {
            float4 bv = *(const float4*)(B + (size_t)(k0 + bk) * ldb + n0 + bn);
            *(float4*)&Bs[bk][bn] = bv;
        }
        __syncthreads();
#pragma unroll
        for (int kk = 0; kk < 8; kk++) {
            float4 ra0 = *(const float4*)&As[kk][ty * 8];
            float4 ra1 = *(const float4*)&As[kk][ty * 8 + 4];
            float4 rb0 = *(const float4*)&Bs[kk][tx * 8];
            float4 rb1 = *(const float4*)&Bs[kk][tx * 8 + 4];
            float ra[8] = {ra0.x, ra0.y, ra0.z, ra0.w, ra1.x, ra1.y, ra1.z, ra1.w};
            float rb[8] = {rb0.x, rb0.y, rb0.z, rb0.w, rb1.x, rb1.y, rb1.z, rb1.w};
#pragma unroll
            for (int i = 0; i < 8; i++)
#pragma unroll
                for (int j = 0; j < 8; j++) acc[i][j] += ra[i] * rb[j];
        }
        __syncthreads();
    }
#pragma unroll
    for (int i = 0; i < 8; i++) {
        int m = m0 + ty * 8 + i;
#pragma unroll
        for (int j = 0; j < 8; j++) {
            int n = n0 + tx * 8 + j;
            float b = bias1 ? bias1[n] : 0.0f;
            if (bias2) b += bias2[n];
            C[(size_t)m * ldc + n] = acc[i][j] + b;
        }
    }
}

// ---------------- persistent recurrent kernel ----------------
__global__ __launch_bounds__(NT, 1) void recurrent_kernel(
    const float* __restrict__ kb_keys, const float* __restrict__ kb_vals,
    const float* __restrict__ W_ih, const float* __restrict__ W_hh,
    const float* __restrict__ bq2) {
    __shared__ __align__(16) float sm[608];
    float* s_q   = sm;          // [256]  (stage 3)
    float* s_e   = sm + 256;    // [<=80] (stage 3)
    float* s_val = sm;          // [512]  (stage 5, reuse)
    float* s_go  = sm + 512;    // [16]   (stage 5)

    const int tid = threadIdx.x;
    const int warp = tid >> 5, lane = tid & 31;
    const int b = blockIdx.x;
    const int gw = b * 16 + warp;
    const int r0 = (b * NKB) / NB;
    const int r1 = ((b + 1) * NKB) / NB;

    unsigned tgt = g_gen + 1;

    for (int t = 0; t < SEQ; t++) {
        const float* hxo = (t & 1) ? g_hxB : g_hxA;
        float* hxn = (t & 1) ? g_hxA : g_hxB;

        // ---- S1: qh[j] = tanh(hx . Wq1T[j] + A1[t][j]) ; warp-per-output ----
        if (gw < QIN) {
            const float4* w = (const float4*)(g_Wq1T + (size_t)gw * STATE);
            const float4* h4 = (const float4*)hxo;
            float a = 0.0f;
#pragma unroll
            for (int i = 0; i < 8; i++) a += dot4(w[lane + 32 * i], h4[lane + 32 * i]);
            a = wred(a);
            if (lane == 0) g_qh[gw] = tanhf(a + g_A1[(size_t)t * QIN + gw]);
        }
        grid_sync(tgt);

        // ---- S2: q[j] = qh . Wq2T[j] + bq2[j] ; warp-per-output ----
        if (gw < QUERY) {
            const float4* w = (const float4*)(g_Wq2T + (size_t)gw * QIN);
            const float4* q4 = (const float4*)g_qh;
            float a = 0.0f;
#pragma unroll
            for (int i = 0; i < 16; i++) a += dot4(w[lane + 32 * i], q4[lane + 32 * i]);
            a = wred(a);
            if (lane == 0) g_q[gw] = a + bq2[gw];
        }
        grid_sync(tgt);

        // ---- S3: per-block KB slice: scores -> exp -> partial val & z ----
        if (tid < QUERY) s_q[tid] = g_q[tid];
        __syncthreads();
        {
            const float4* q4 = (const float4*)s_q;
            for (int r = r0 + warp; r < r1; r += 16) {
                const float4* kr = (const float4*)(kb_keys + (size_t)r * QUERY);
                float a = dot4(kr[lane], q4[lane]) + dot4(kr[lane + 32], q4[lane + 32]);
                a = wred(a);
                if (lane == 0) s_e[r - r0] = expf(a);
            }
        }
        __syncthreads();
        {
            const int nl = r1 - r0;
            float a = 0.0f;
            const float* kv = kb_vals + (size_t)r0 * VALUE + tid;
            for (int i = 0; i < nl; i++) a += s_e[i] * kv[(size_t)i * VALUE];
            g_pval[(size_t)tid * 152 + b] = a;
            if (warp == 0) {
                float z = 0.0f;
                for (int i = lane; i < nl; i += 32) z += s_e[i];
                z = wred(z);
                if (lane == 0) g_pz[b] = z;
            }
        }
        grid_sync(tgt);

        // ---- S4b: reduce partials -> val[512], invZ ----
        if (gw < VALUE) {
            float a = 0.0f;
#pragma unroll
            for (int i = 0; i < 5; i++) {
                int bb = lane + 32 * i;
                if (bb < NB) a += g_pval[(size_t)gw * 152 + bb];
            }
            a = wred(a);
            if (lane == 0) g_val[gw] = a;
        } else if (gw == VALUE) {
            float z = 0.0f;
#pragma unroll
            for (int i = 0; i < 5; i++) {
                int bb = lane + 32 * i;
                if (bb < NB) z += g_pz[bb];
            }
            z = wred(z);
            if (lane == 0) g_invZ = 1.0f / z;
        }
        grid_sync(tgt);

        // ---- S5: gates + LSTM update; idle blocks write output rows ----
        float invZ = g_invZ;
        if (b < 128) {
            if (tid < VALUE) s_val[tid] = g_val[tid] * invZ;
        } else if (b == 128) {
            if (tid < VALUE) g_dec_in[(size_t)t * DECIN + EMBD + tid] = g_val[tid] * invZ;
        } else if (b == 129) {
            for (int i = tid; i < STATE; i += NT)
                g_dec_in[(size_t)t * DECIN + EMBD + VALUE + i] = hxo[i];
        }
        __syncthreads();

        int s = b * 8 + (warp >> 1);
        int half = warp & 1;
        int sl = warp >> 1;
        float a0 = 0.0f, a1 = 0.0f;
        if (b < 128) {
            int j0 = half * 2048 + (s & 1023) + (half ? 0 : 0); // j0 = half*2048 + s_local
            j0 = half * 2048 + (b * 8 + sl);                    // s in [0,1024)
            int j1 = j0 + 1024;
            const float4* v4 = (const float4*)s_val;
            const float4* h4 = (const float4*)hxo;
            const float4* wv0 = (const float4*)(W_ih + (size_t)j0 * LSTMIN + EMBD);
            const float4* wv1 = (const float4*)(W_ih + (size_t)j1 * LSTMIN + EMBD);
            const float4* wh0 = (const float4*)(W_hh + (size_t)j0 * STATE);
            const float4* wh1 = (const float4*)(W_hh + (size_t)j1 * STATE);
#pragma unroll
            for (int i = 0; i < 4; i++) {
                float4 vv = v4[lane + 32 * i];
                a0 += dot4(wv0[lane + 32 * i], vv);
                a1 += dot4(wv1[lane + 32 * i], vv);
            }
#pragma unroll
            for (int i = 0; i < 8; i++) {
                float4 hh = h4[lane + 32 * i];
                a0 += dot4(wh0[lane + 32 * i], hh);
                a1 += dot4(wh1[lane + 32 * i], hh);
            }
            a0 = wred(a0); a1 = wred(a1);
            if (lane == 0) {
                a0 += g_Gx[(size_t)t * 4096 + j0];
                a1 += g_Gx[(size_t)t * 4096 + j1];
                if (half) { s_go[sl * 2] = a0; s_go[sl * 2 + 1] = a1; }
            }
        }
        __syncthreads();
        if (b < 128 && half == 0 && lane == 0) {
            // a0 = gate i, a1 = gate f ; partner warp left g,o in smem
            float gg = s_go[sl * 2], oo = s_go[sl * 2 + 1];
            float c_old = g_cx[s];
            float cn = sigmoidf_(a1) * c_old + sigmoidf_(a0) * tanhf(gg);
            float hn = sigmoidf_(oo) * tanhf(cn);
            g_cx[s] = cn;
            hxn[s] = hn;
        }
        grid_sync(tgt);
    }
}

// ---------------- row-wise log_softmax over [SEQ, NTOK] in place ----------------
__global__ __launch_bounds__(256) void logsoftmax_kernel(float* __restrict__ out) {
    __shared__ float red[8];
    const int row = blockIdx.x;
    float* x = out + (size_t)row * NTOK;
    const int tid = threadIdx.x;

    float m = -1e30f;
    for (int i = tid; i < NTOK; i += 256) m = fmaxf(m, x[i]);
#pragma unroll
    for (int o = 16; o; o >>= 1) m = fmaxf(m, __shfl_xor_sync(0xffffffffu, m, o));
    if ((tid & 31) == 0) red[tid >> 5] = m;
    __syncthreads();
    float mm = red[0];
#pragma unroll
    for (int i = 1; i < 8; i++) mm = fmaxf(mm, red[i]);
    __syncthreads();

    float sum = 0.0f;
    for (int i = tid; i < NTOK; i += 256) sum += expf(x[i] - mm);
    sum = wred(sum);
    if ((tid & 31) == 0) red[tid >> 5] = sum;
    __syncthreads();
    float ss = 0.0f;
#pragma unroll
    for (int i = 0; i < 8; i++) ss += red[i];
    float lse = mm + logf(ss);

    for (int i = tid; i < NTOK; i += 256) x[i] = x[i] - lse;
}

// ---------------- launch ----------------
extern "C" void kernel_launch(void* const* d_in, const int* in_sizes, int n_in,
                              void* d_out, int out_size) {
    const int*   ids  = (const int*)d_in[0];
    const float* encW = (const float*)d_in[1];
    const float* Wq1  = (const float*)d_in[2];
    const float* bq1  = (const float*)d_in[3];
    const float* Wq2  = (const float*)d_in[4];
    const float* bq2  = (const float*)d_in[5];
    const float* kbk  = (const float*)d_in[6];
    const float* kbv  = (const float*)d_in[7];
    const float* Wih  = (const float*)d_in[8];
    const float* bih  = (const float*)d_in[9];
    const float* Whh  = (const float*)d_in[10];
    const float* bhh  = (const float*)d_in[11];
    const float* Wdec = (const float*)d_in[12];
    const float* bdec = (const float*)d_in[13];
    float* out = (float*)d_out;

    float *p_dec, *p_A1, *p_Gx, *p_Wq1T, *p_Wq2T;
    cudaGetSymbolAddress((void**)&p_dec,  g_dec_in);
    cudaGetSymbolAddress((void**)&p_A1,   g_A1);
    cudaGetSymbolAddress((void**)&p_Gx,   g_Gx);
    cudaGetSymbolAddress((void**)&p_Wq1T, g_Wq1T);
    cudaGetSymbolAddress((void**)&p_Wq2T, g_Wq2T);

    dim3 tb(32, 8);
    embed_init_kernel<<<SEQ, 256>>>(ids, encW);
    // Wq1T[j][k] = Wq1[k][j], k<1024 (hx rows)
    transpose_kernel<<<dim3(QIN / 32, STATE / 32), tb>>>(Wq1, p_Wq1T, STATE, QIN);
    // Wq2T[j][k] = Wq2[k][j]
    transpose_kernel<<<dim3(QUERY / 32, QIN / 32), tb>>>(Wq2, p_Wq2T, QIN, QUERY);
    // A1 = emb @ Wq1[1024:, :] + bq1   (B not transposed)
    sgemm_kernel<false><<<dim3(QIN / 128, SEQ / 128), 256>>>(
        p_dec, DECIN, Wq1 + (size_t)STATE * QIN, QIN, p_A1, QIN, EMBD, bq1, nullptr);
    // Gx = emb @ W_ih[:, :1024]^T + b_ih + b_hh   (B transposed, row stride 1536)
    sgemm_kernel<true><<<dim3(4096 / 128, SEQ / 128), 256>>>(
        p_dec, DECIN, Wih, LSTMIN, p_Gx, 4096, EMBD, bih, bhh);
    // sequential recurrence (persistent, grid-synced)
    recurrent_kernel<<<NB, NT>>>(kbk, kbv, Wih, Whh, bq2);
    // decoder GEMM: [SEQ, DECIN] @ W_dec^T + b_dec
    sgemm_kernel<true><<<dim3(NTOK / 128, SEQ / 128), 256>>>(
        p_dec, DECIN, Wdec, DECIN, out, NTOK, DECIN, bdec, nullptr);
    logsoftmax_kernel<<<SEQ, 256>>>(out);
}